// round 1
// baseline (speedup 1.0000x reference)
#include <cuda_runtime.h>
#include <cuda_bf16.h>
#include <math.h>

// Problem constants
#define B_    256
#define P_    100
#define ENC_  1536
#define DEC_  512
#define ATT_  256
#define EMB_  256
#define V_    193
#define T_    150
#define T1_   151
#define XDIM_ 1792   // EMB + ENC
#define G4_   2048   // 4*DEC
#define NCAT_ 3840   // ATT + ENC + G4
#define HOFF_ 1792   // ATT + ENC (offset of W_hh block in hproj)

// Scratch (device globals: allocation-free per harness rules)
__device__ float g_h[B_ * DEC_];
__device__ float g_c[B_ * DEC_];
__device__ float g_mean[B_ * ENC_];
__device__ float g_att1[B_ * P_ * ATT_];
__device__ float g_hproj[B_ * NCAT_];
__device__ float g_x[B_ * XDIM_];
__device__ float g_Wcat[DEC_ * NCAT_];
__device__ float g_bcat[NCAT_];

__device__ __forceinline__ float sigmoidf_(float x) {
    return 1.0f / (1.0f + expf(-x));
}

// ---------------------------------------------------------------------------
// Generic 64x64 tile SGEMM: C[M,N] = A[M,K] @ W[K,N] (+ bias[n])
// 256 threads, BK=16, 4x4 per thread. Requires M%64==0, N%64==0, K%16==0.
// SKIP: rows are batch indices sorted by caption length descending; a row-tile
// whose first row is inactive at step t is entirely inactive -> early exit.
// ---------------------------------------------------------------------------
template <bool BIAS, bool SKIP>
__global__ void sgemm64(const float* __restrict__ A, const float* __restrict__ W,
                        const float* __restrict__ bias, float* __restrict__ C,
                        int K, int N, const int* __restrict__ len, int t) {
    const int row0 = blockIdx.y * 64;
    if (SKIP) {
        if (t >= len[row0] - 1) return;   // sorted descending -> whole tile inactive
    }
    const int col0 = blockIdx.x * 64;
    const int tid = threadIdx.x;
    const int tx = tid % 16;   // col quad
    const int ty = tid / 16;   // row quad

    __shared__ float As[16][64];   // [k][row]
    __shared__ float Bs[16][64];   // [k][col]

    float acc[4][4];
#pragma unroll
    for (int i = 0; i < 4; i++)
#pragma unroll
        for (int j = 0; j < 4; j++) acc[i][j] = 0.0f;

    const int arow = tid / 4;          // 0..63
    const int acol = (tid % 4) * 4;    // 0,4,8,12
    const int brow = tid / 16;         // 0..15
    const int bcol = (tid % 16) * 4;   // 0..60

    for (int k0 = 0; k0 < K; k0 += 16) {
        float4 av = *(const float4*)(A + (size_t)(row0 + arow) * K + k0 + acol);
        As[acol + 0][arow] = av.x;
        As[acol + 1][arow] = av.y;
        As[acol + 2][arow] = av.z;
        As[acol + 3][arow] = av.w;
        float4 bv = *(const float4*)(W + (size_t)(k0 + brow) * N + col0 + bcol);
        *(float4*)&Bs[brow][bcol] = bv;
        __syncthreads();
#pragma unroll
        for (int kk = 0; kk < 16; kk++) {
            float4 a = *(const float4*)&As[kk][ty * 4];
            float4 b = *(const float4*)&Bs[kk][tx * 4];
            float ar[4] = {a.x, a.y, a.z, a.w};
            float br[4] = {b.x, b.y, b.z, b.w};
#pragma unroll
            for (int i = 0; i < 4; i++)
#pragma unroll
                for (int j = 0; j < 4; j++) acc[i][j] += ar[i] * br[j];
        }
        __syncthreads();
    }

#pragma unroll
    for (int i = 0; i < 4; i++) {
        float* crow = C + (size_t)(row0 + ty * 4 + i) * N + col0 + tx * 4;
#pragma unroll
        for (int j = 0; j < 4; j++) {
            float v = acc[i][j];
            if (BIAS) v += bias[col0 + tx * 4 + j];
            crow[j] = v;
        }
    }
}

// ---------------------------------------------------------------------------
// mean_enc[b,e] = mean over P of encoder_out[b,p,e]
// ---------------------------------------------------------------------------
__global__ void mean_kernel(const float* __restrict__ enc, float* __restrict__ mean) {
    const int b = blockIdx.y;
    const int e = blockIdx.x * 256 + threadIdx.x;
    const float* ep = enc + ((size_t)b * P_) * ENC_ + e;
    float s = 0.0f;
#pragma unroll 4
    for (int p = 0; p < P_; p++) s += ep[(size_t)p * ENC_];
    mean[(size_t)b * ENC_ + e] = s * (1.0f / P_);
}

// ---------------------------------------------------------------------------
// Build concatenated weight [DEC, NCAT] = [W_dec_att | W_f_beta | W_hh] and
// concatenated bias (b_dec_att | b_f_beta | b_hh).
// ---------------------------------------------------------------------------
__global__ void wcat_kernel(const float* __restrict__ Wda, const float* __restrict__ Wfb,
                            const float* __restrict__ Whh, const float* __restrict__ bda,
                            const float* __restrict__ bfb, const float* __restrict__ bhh,
                            float* __restrict__ Wcat, float* __restrict__ bcat) {
    const int idx = blockIdx.x * 256 + threadIdx.x;
    if (idx >= DEC_ * NCAT_) return;
    const int k = idx / NCAT_;
    const int n = idx % NCAT_;
    float v;
    if (n < ATT_)          v = Wda[k * ATT_ + n];
    else if (n < HOFF_)    v = Wfb[k * ENC_ + (n - ATT_)];
    else                   v = Whh[k * G4_ + (n - HOFF_)];
    Wcat[idx] = v;
    if (k == 0) {
        float bv;
        if (n < ATT_)       bv = bda[n];
        else if (n < HOFF_) bv = bfb[n - ATT_];
        else                bv = bhh[n - HOFF_];
        bcat[n] = bv;
    }
}

// ---------------------------------------------------------------------------
// Per-batch attention: scores e_p = relu(att1[b,p,:] + att2[b,:]) . W_full_att,
// softmax over p, awe = gate * sum_p alpha_p enc[b,p,:], build x = [emb_t, awe].
// One block per batch element; inactive batches exit.
// ---------------------------------------------------------------------------
__global__ void attn_kernel(const float* __restrict__ enc, const float* __restrict__ att1,
                            const float* __restrict__ Wfull,
                            const int* __restrict__ caps, const float* __restrict__ emb,
                            const float* __restrict__ hproj, float* __restrict__ x,
                            const int* __restrict__ len, int t) {
    const int b = blockIdx.x;
    if (t >= len[b] - 1) return;
    const int tid = threadIdx.x;
    const int warp = tid >> 5, lane = tid & 31;

    __shared__ float att2s[ATT_];
    __shared__ float wf[ATT_];
    __shared__ float es[P_ + 4];

    att2s[tid] = hproj[(size_t)b * NCAT_ + tid];
    wf[tid] = Wfull[tid];
    __syncthreads();

    // scores
    for (int p = warp; p < P_; p += 8) {
        const float* a1 = att1 + ((size_t)(b * P_ + p)) * ATT_;
        float part = 0.0f;
#pragma unroll 4
        for (int j = lane; j < ATT_; j += 32)
            part += fmaxf(a1[j] + att2s[j], 0.0f) * wf[j];
#pragma unroll
        for (int o = 16; o; o >>= 1) part += __shfl_xor_sync(0xffffffffu, part, o);
        if (lane == 0) es[p] = part;
    }
    __syncthreads();

    // softmax over P (warp 0)
    if (tid < 32) {
        float m = -1e30f;
        for (int p = tid; p < P_; p += 32) m = fmaxf(m, es[p]);
#pragma unroll
        for (int o = 16; o; o >>= 1) m = fmaxf(m, __shfl_xor_sync(0xffffffffu, m, o));
        float s = 0.0f;
        for (int p = tid; p < P_; p += 32) {
            float ex = expf(es[p] - m);
            es[p] = ex;
            s += ex;
        }
#pragma unroll
        for (int o = 16; o; o >>= 1) s += __shfl_xor_sync(0xffffffffu, s, o);
        float inv = 1.0f / s;
        for (int p = tid; p < P_; p += 32) es[p] *= inv;
    }
    __syncthreads();

    // embedding part of x
    const int token = caps[b * T1_ + t];
    x[(size_t)b * XDIM_ + tid] = emb[(size_t)token * EMB_ + tid];

    // awe part of x (gated)
    for (int e0 = tid; e0 < ENC_; e0 += 256) {
        const float* ep = enc + ((size_t)b * P_) * ENC_ + e0;
        float acc = 0.0f;
#pragma unroll 4
        for (int p = 0; p < P_; p++) acc += es[p] * ep[(size_t)p * ENC_];
        float gate = sigmoidf_(hproj[(size_t)b * NCAT_ + ATT_ + e0]);
        x[(size_t)b * XDIM_ + EMB_ + e0] = gate * acc;
    }
}

// ---------------------------------------------------------------------------
// Fused gates GEMM + LSTM cell.
// gates[b, g*512+d] = x[b,:] @ W_ih[:, g*512+d] + b_ih + hproj_hh + (b_hh baked
// into hproj). Block computes rows [row0,row0+64) x 32 d's x 4 gates, then does
// the cell update in registers and writes masked h,c.
// ---------------------------------------------------------------------------
__global__ void gates_kernel(const float* __restrict__ x, const float* __restrict__ Wih,
                             const float* __restrict__ bih, const float* __restrict__ hproj,
                             float* __restrict__ h, float* __restrict__ c,
                             const int* __restrict__ len, int t) {
    const int row0 = blockIdx.y * 64;
    if (t >= len[row0] - 1) return;
    const int d0 = blockIdx.x * 32;
    const int tid = threadIdx.x;
    const int rp = tid / 8;   // row pair 0..31
    const int rq = tid % 8;   // d quad 0..7

    __shared__ float As[16][64];    // [k][row]
    __shared__ float Ws[16][128];   // [k][g*32 + dl]

    float acc[2][4][4];
#pragma unroll
    for (int r = 0; r < 2; r++)
#pragma unroll
        for (int g = 0; g < 4; g++)
#pragma unroll
            for (int j = 0; j < 4; j++) acc[r][g][j] = 0.0f;

    const int arow = tid / 4;
    const int acol = (tid % 4) * 4;
    const int cq = tid % 32;        // col quad 0..31 of the 128-wide W tile
    const int ccol = cq * 4;
    const int wg = ccol / 32;       // gate index (quad never straddles)
    const int wdl = ccol % 32;
    const int kr0 = tid / 32;       // 0..7

    for (int k0 = 0; k0 < XDIM_; k0 += 16) {
        float4 av = *(const float4*)(x + (size_t)(row0 + arow) * XDIM_ + k0 + acol);
        As[acol + 0][arow] = av.x;
        As[acol + 1][arow] = av.y;
        As[acol + 2][arow] = av.z;
        As[acol + 3][arow] = av.w;
#pragma unroll
        for (int rr = 0; rr < 2; rr++) {
            int kr = kr0 + rr * 8;
            float4 wv = *(const float4*)(Wih + (size_t)(k0 + kr) * G4_ + wg * DEC_ + d0 + wdl);
            *(float4*)&Ws[kr][ccol] = wv;
        }
        __syncthreads();
#pragma unroll
        for (int kk = 0; kk < 16; kk++) {
            float a0 = As[kk][rp * 2 + 0];
            float a1 = As[kk][rp * 2 + 1];
#pragma unroll
            for (int g = 0; g < 4; g++) {
                float4 w = *(const float4*)&Ws[kk][g * 32 + rq * 4];
                float wr[4] = {w.x, w.y, w.z, w.w};
#pragma unroll
                for (int j = 0; j < 4; j++) {
                    acc[0][g][j] += a0 * wr[j];
                    acc[1][g][j] += a1 * wr[j];
                }
            }
        }
        __syncthreads();
    }

#pragma unroll
    for (int rr = 0; rr < 2; rr++) {
        const int b = row0 + rp * 2 + rr;
        if (t >= len[b] - 1) continue;   // per-row mask
#pragma unroll
        for (int j = 0; j < 4; j++) {
            const int d = d0 + rq * 4 + j;
            const size_t hb = (size_t)b * NCAT_ + HOFF_;
            float vi = acc[rr][0][j] + hproj[hb + 0 * DEC_ + d] + bih[0 * DEC_ + d];
            float vf = acc[rr][1][j] + hproj[hb + 1 * DEC_ + d] + bih[1 * DEC_ + d];
            float vg = acc[rr][2][j] + hproj[hb + 2 * DEC_ + d] + bih[2 * DEC_ + d];
            float vo = acc[rr][3][j] + hproj[hb + 3 * DEC_ + d] + bih[3 * DEC_ + d];
            float c_old = c[(size_t)b * DEC_ + d];
            float ii = sigmoidf_(vi);
            float ff = sigmoidf_(vf);
            float gg = tanhf(vg);
            float oo = sigmoidf_(vo);
            float cn = ff * c_old + ii * gg;
            float hn = oo * tanhf(cn);
            c[(size_t)b * DEC_ + d] = cn;
            h[(size_t)b * DEC_ + d] = hn;
        }
    }
}

// ---------------------------------------------------------------------------
// preds[b,t,:] = active ? h[b,:] @ W_fc + b_fc : 0
// One block per batch element.
// ---------------------------------------------------------------------------
__global__ void preds_kernel(const float* __restrict__ Wfc, const float* __restrict__ bfc,
                             const float* __restrict__ h, float* __restrict__ out,
                             const int* __restrict__ len, int t) {
    const int b = blockIdx.x;
    const int tid = threadIdx.x;
    float* o = out + ((size_t)b * T_ + t) * V_;
    if (t >= len[b] - 1) {
        if (tid < V_) o[tid] = 0.0f;
        return;
    }
    __shared__ float hs[DEC_];
    hs[tid] = h[(size_t)b * DEC_ + tid];
    hs[tid + 256] = h[(size_t)b * DEC_ + tid + 256];
    __syncthreads();
    if (tid < V_) {
        float acc = bfc[tid];
#pragma unroll 8
        for (int k = 0; k < DEC_; k++) acc += hs[k] * Wfc[(size_t)k * V_ + tid];
        o[tid] = acc;
    }
}

// ---------------------------------------------------------------------------
extern "C" void kernel_launch(void* const* d_in, const int* in_sizes, int n_in,
                              void* d_out, int out_size) {
    const float* enc        = (const float*)d_in[0];
    const int*   caps       = (const int*)d_in[1];
    const int*   lens       = (const int*)d_in[2];
    const float* emb        = (const float*)d_in[3];
    const float* W_enc_att  = (const float*)d_in[4];
    const float* b_enc_att  = (const float*)d_in[5];
    const float* W_dec_att  = (const float*)d_in[6];
    const float* b_dec_att  = (const float*)d_in[7];
    const float* W_full_att = (const float*)d_in[8];
    // d_in[9] = b_full_att (constant shift, softmax-invariant; unused)
    const float* W_init_h   = (const float*)d_in[10];
    const float* b_init_h   = (const float*)d_in[11];
    const float* W_init_c   = (const float*)d_in[12];
    const float* b_init_c   = (const float*)d_in[13];
    const float* W_f_beta   = (const float*)d_in[14];
    const float* b_f_beta   = (const float*)d_in[15];
    const float* W_ih       = (const float*)d_in[16];
    const float* b_ih       = (const float*)d_in[17];
    const float* W_hh       = (const float*)d_in[18];
    const float* b_hh       = (const float*)d_in[19];
    const float* W_fc       = (const float*)d_in[20];
    const float* b_fc       = (const float*)d_in[21];
    float* out = (float*)d_out;

    float *ph, *pc, *pmean, *patt1, *phproj, *px, *pWcat, *pbcat;
    cudaGetSymbolAddress((void**)&ph,     g_h);
    cudaGetSymbolAddress((void**)&pc,     g_c);
    cudaGetSymbolAddress((void**)&pmean,  g_mean);
    cudaGetSymbolAddress((void**)&patt1,  g_att1);
    cudaGetSymbolAddress((void**)&phproj, g_hproj);
    cudaGetSymbolAddress((void**)&px,     g_x);
    cudaGetSymbolAddress((void**)&pWcat,  g_Wcat);
    cudaGetSymbolAddress((void**)&pbcat,  g_bcat);

    // ---- precompute ----
    mean_kernel<<<dim3(ENC_ / 256, B_), 256>>>(enc, pmean);
    wcat_kernel<<<(DEC_ * NCAT_ + 255) / 256, 256>>>(W_dec_att, W_f_beta, W_hh,
                                                     b_dec_att, b_f_beta, b_hh,
                                                     pWcat, pbcat);
    // h0 = mean @ W_init_h + b ; c0 = mean @ W_init_c + b
    sgemm64<true, false><<<dim3(DEC_ / 64, B_ / 64), 256>>>(pmean, W_init_h, b_init_h, ph,
                                                            ENC_, DEC_, nullptr, 0);
    sgemm64<true, false><<<dim3(DEC_ / 64, B_ / 64), 256>>>(pmean, W_init_c, b_init_c, pc,
                                                            ENC_, DEC_, nullptr, 0);
    // att1 = encoder_out @ W_enc_att + b  (M = B*P)
    sgemm64<true, false><<<dim3(ATT_ / 64, (B_ * P_) / 64), 256>>>(enc, W_enc_att, b_enc_att,
                                                                   patt1, ENC_, ATT_,
                                                                   nullptr, 0);

    // ---- timestep loop ----
    for (int t = 0; t < T_; t++) {
        // hproj = h @ [W_dec_att | W_f_beta | W_hh] + [b_dec_att|b_f_beta|b_hh]
        sgemm64<true, true><<<dim3(NCAT_ / 64, B_ / 64), 256>>>(ph, pWcat, pbcat, phproj,
                                                                DEC_, NCAT_, lens, t);
        attn_kernel<<<B_, 256>>>(enc, patt1, W_full_att, caps, emb, phproj, px, lens, t);
        gates_kernel<<<dim3(DEC_ / 32, B_ / 64), 256>>>(px, W_ih, b_ih, phproj, ph, pc,
                                                        lens, t);
        preds_kernel<<<B_, 256>>>(W_fc, b_fc, ph, out, lens, t);
    }
}

// round 3
// speedup vs baseline: 1.7837x; 1.7837x over previous
#include <cuda_runtime.h>
#include <math.h>

// Problem constants
#define B_    256
#define P_    100
#define ENC_  1536
#define DEC_  512
#define ATT_  256
#define EMB_  256
#define V_    193
#define T_    150
#define T1_   151
#define N1_   1792   // att2(256) + f_beta(1536)
#define K2_   2048   // awe(1536) + h(512)
#define N2_   2048   // 4*DEC gate-interleaved

typedef unsigned long long ull;

// Scratch (device globals: allocation-free per harness rules)
__device__ float g_h[B_ * DEC_];
__device__ float g_c[B_ * DEC_];
__device__ float g_mean[B_ * ENC_];
__device__ float g_att1[B_ * P_ * ATT_];
__device__ float g_hproj[B_ * N1_];
__device__ float g_x[B_ * K2_];          // [gated awe (1536) | h (512)]
__device__ float g_Wcat1[DEC_ * N1_];    // [W_dec_att | W_f_beta]
__device__ float g_bcat1[N1_];
__device__ float g_Wcat2[K2_ * N2_];     // rows: [W_ih_enc ; W_hh], cols interleaved d*4+g
__device__ float g_embW[V_ * N2_];       // emb@W_ih_emb + b_ih + b_hh, cols interleaved

__device__ __forceinline__ float sigmoidf_(float x) { return 1.0f / (1.0f + expf(-x)); }

__device__ __forceinline__ ull ffma2(ull a, ull b, ull c) {
    ull d;
    asm("fma.rn.f32x2 %0, %1, %2, %3;" : "=l"(d) : "l"(a), "l"(b), "l"(c));
    return d;
}
__device__ __forceinline__ ull pack2(float x, float y) {
    ull r;
    asm("mov.b64 %0, {%1, %2};" : "=l"(r) : "f"(x), "f"(y));
    return r;
}
__device__ __forceinline__ void unpack2(ull v, float& x, float& y) {
    asm("mov.b64 {%0, %1}, %2;" : "=f"(x), "=f"(y) : "l"(v));
}

// ---------------------------------------------------------------------------
// Core 32x128 GEMM tile, BK=32, 256 threads, 4x4 per thread, f32x2 FMAs.
// acc[p][j]: p = row-pair (rows rbase+2p, rbase+2p+1), j = col.
// Requires K%32==0, rows0+32<=M, cols0+128<=N. Register-prefetch pipelining.
// ---------------------------------------------------------------------------
__device__ __forceinline__ void gemm_tile(const float* __restrict__ A, int lda,
                                          const float* __restrict__ W, int N, int K,
                                          int rows0, int cols0,
                                          float (*As)[34], float (*Bs)[128],
                                          ull acc[2][4]) {
    const int tid  = threadIdx.x;
    const int arow = tid >> 3;           // 0..31
    const int acol = (tid & 7) << 2;     // 0..28
    const int brow = tid >> 5;           // 0..7
    const int bcol = (tid & 31) << 2;    // 0..124
    const int rbase = (tid >> 5) << 2;   // 0..28 (warp -> row group)
    const int cbase = (tid & 31) << 2;   // 0..124

    float4 aReg = *(const float4*)(A + (size_t)(rows0 + arow) * lda + acol);
    float4 bReg[4];
#pragma unroll
    for (int r = 0; r < 4; r++)
        bReg[r] = *(const float4*)(W + (size_t)(brow + 8 * r) * N + cols0 + bcol);

    for (int k0 = 0; k0 < K; k0 += 32) {
        As[acol + 0][arow] = aReg.x;
        As[acol + 1][arow] = aReg.y;
        As[acol + 2][arow] = aReg.z;
        As[acol + 3][arow] = aReg.w;
#pragma unroll
        for (int r = 0; r < 4; r++)
            *(float4*)&Bs[brow + 8 * r][bcol] = bReg[r];
        __syncthreads();
        if (k0 + 32 < K) {
            aReg = *(const float4*)(A + (size_t)(rows0 + arow) * lda + k0 + 32 + acol);
#pragma unroll
            for (int r = 0; r < 4; r++)
                bReg[r] = *(const float4*)(W + (size_t)(k0 + 32 + brow + 8 * r) * N + cols0 + bcol);
        }
#pragma unroll
        for (int kk = 0; kk < 32; kk++) {
            ull a01 = *(const ull*)&As[kk][rbase];
            ull a23 = *(const ull*)&As[kk][rbase + 2];
            float4 b4 = *(const float4*)&Bs[kk][cbase];
            ull b0 = pack2(b4.x, b4.x);
            ull b1 = pack2(b4.y, b4.y);
            ull b2 = pack2(b4.z, b4.z);
            ull b3 = pack2(b4.w, b4.w);
            acc[0][0] = ffma2(a01, b0, acc[0][0]);
            acc[0][1] = ffma2(a01, b1, acc[0][1]);
            acc[0][2] = ffma2(a01, b2, acc[0][2]);
            acc[0][3] = ffma2(a01, b3, acc[0][3]);
            acc[1][0] = ffma2(a23, b0, acc[1][0]);
            acc[1][1] = ffma2(a23, b1, acc[1][1]);
            acc[1][2] = ffma2(a23, b2, acc[1][2]);
            acc[1][3] = ffma2(a23, b3, acc[1][3]);
        }
        __syncthreads();
    }
}

// ---------------------------------------------------------------------------
// Generic GEMM + bias: C[M,N] = A@W + bias. SKIP: sorted-length row-tile skip.
// ---------------------------------------------------------------------------
template <bool SKIP>
__global__ void __launch_bounds__(256)
gemm_f2(const float* __restrict__ A, int lda,
        const float* __restrict__ W, int N, int K,
        const float* __restrict__ bias, float* __restrict__ C,
        const int* __restrict__ len, int t) {
    __shared__ __align__(16) float As[32][34];
    __shared__ __align__(16) float Bs[32][128];
    const int rows0 = blockIdx.y * 32;
    if (SKIP) {
        if (t >= len[rows0] - 1) return;
    }
    const int cols0 = blockIdx.x * 128;
    ull acc[2][4] = {{0ull, 0ull, 0ull, 0ull}, {0ull, 0ull, 0ull, 0ull}};
    gemm_tile(A, lda, W, N, K, rows0, cols0, As, Bs, acc);

    const int tid = threadIdx.x;
    const int rbase = (tid >> 5) << 2;
    const int cbase = (tid & 31) << 2;
    float4 bv = *(const float4*)(bias + cols0 + cbase);
#pragma unroll
    for (int p = 0; p < 2; p++) {
        float lo[4], hi[4];
#pragma unroll
        for (int j = 0; j < 4; j++) unpack2(acc[p][j], lo[j], hi[j]);
        int r = rows0 + rbase + 2 * p;
        float4 v0 = make_float4(lo[0] + bv.x, lo[1] + bv.y, lo[2] + bv.z, lo[3] + bv.w);
        float4 v1 = make_float4(hi[0] + bv.x, hi[1] + bv.y, hi[2] + bv.z, hi[3] + bv.w);
        *(float4*)(C + (size_t)r * N + cols0 + cbase) = v0;
        *(float4*)(C + (size_t)(r + 1) * N + cols0 + cbase) = v1;
    }
}

// ---------------------------------------------------------------------------
// Fused gates GEMM + LSTM cell. A = g_x [awe|h] (K=2048), W = g_Wcat2 (cols
// interleaved d*4+g). Epilogue: + embW[token] lookup (includes b_ih+b_hh),
// then i,f,g,o -> c,h update, masked per row.
// ---------------------------------------------------------------------------
__global__ void __launch_bounds__(256)
gates_fused(const float* __restrict__ x, const float* __restrict__ W,
            const float* __restrict__ embW, const int* __restrict__ caps,
            float* __restrict__ h, float* __restrict__ c,
            const int* __restrict__ len, int t) {
    __shared__ __align__(16) float As[32][34];
    __shared__ __align__(16) float Bs[32][128];
    const int rows0 = blockIdx.y * 32;
    if (t >= len[rows0] - 1) return;
    const int cols0 = blockIdx.x * 128;
    ull acc[2][4] = {{0ull, 0ull, 0ull, 0ull}, {0ull, 0ull, 0ull, 0ull}};
    gemm_tile(x, K2_, W, N2_, K2_, rows0, cols0, As, Bs, acc);

    const int tid = threadIdx.x;
    const int rbase = (tid >> 5) << 2;
    const int cbase = (tid & 31) << 2;
    const int d = (cols0 + cbase) >> 2;   // all 4 cols of this thread = gates of unit d

#pragma unroll
    for (int p = 0; p < 2; p++) {
        float lo[4], hi[4];
#pragma unroll
        for (int j = 0; j < 4; j++) unpack2(acc[p][j], lo[j], hi[j]);
#pragma unroll
        for (int sub = 0; sub < 2; sub++) {
            const int b = rows0 + rbase + 2 * p + sub;
            if (t < len[b] - 1) {
                float gv0 = sub ? hi[0] : lo[0];
                float gv1 = sub ? hi[1] : lo[1];
                float gv2 = sub ? hi[2] : lo[2];
                float gv3 = sub ? hi[3] : lo[3];
                const int token = caps[b * T1_ + t];
                float4 ew = *(const float4*)(embW + (size_t)token * N2_ + cols0 + cbase);
                float vi = gv0 + ew.x;
                float vf = gv1 + ew.y;
                float vg = gv2 + ew.z;
                float vo = gv3 + ew.w;
                float c_old = c[(size_t)b * DEC_ + d];
                float ii = sigmoidf_(vi);
                float ff = sigmoidf_(vf);
                float gg = tanhf(vg);
                float oo = sigmoidf_(vo);
                float cn = ff * c_old + ii * gg;
                float hn = oo * tanhf(cn);
                c[(size_t)b * DEC_ + d] = cn;
                h[(size_t)b * DEC_ + d] = hn;
            }
        }
    }
}

// ---------------------------------------------------------------------------
// mean_enc[b,e] = mean over P of encoder_out[b,p,e]
// ---------------------------------------------------------------------------
__global__ void mean_kernel(const float* __restrict__ enc, float* __restrict__ mean) {
    const int b = blockIdx.y;
    const int e = blockIdx.x * 256 + threadIdx.x;
    const float* ep = enc + ((size_t)b * P_) * ENC_ + e;
    float s = 0.0f;
#pragma unroll 4
    for (int p = 0; p < P_; p++) s += ep[(size_t)p * ENC_];
    mean[(size_t)b * ENC_ + e] = s * (1.0f / P_);
}

// ---------------------------------------------------------------------------
// Weight prep
// ---------------------------------------------------------------------------
__global__ void wcat1_kernel(const float* __restrict__ Wda, const float* __restrict__ Wfb,
                             const float* __restrict__ bda, const float* __restrict__ bfb,
                             float* __restrict__ Wc, float* __restrict__ bc) {
    int idx = blockIdx.x * 256 + threadIdx.x;
    if (idx >= DEC_ * N1_) return;
    int k = idx / N1_, n = idx % N1_;
    Wc[idx] = (n < ATT_) ? Wda[k * ATT_ + n] : Wfb[k * ENC_ + (n - ATT_)];
    if (k == 0) bc[n] = (n < ATT_) ? bda[n] : bfb[n - ATT_];
}

__global__ void wcat2_kernel(const float* __restrict__ Wih, const float* __restrict__ Whh,
                             float* __restrict__ Wc) {
    int idx = blockIdx.x * 256 + threadIdx.x;
    if (idx >= K2_ * N2_) return;
    int k = idx / N2_, cp = idx % N2_;
    int dd = cp >> 2, g = cp & 3;
    int oc = g * DEC_ + dd;
    Wc[idx] = (k < 1536) ? Wih[(size_t)(256 + k) * N2_ + oc]
                         : Whh[(size_t)(k - 1536) * N2_ + oc];
}

// embW[v, d*4+g] = sum_k emb[v,k] * W_ih[k, g*512+d] + b_ih + b_hh
__global__ void embw_kernel(const float* __restrict__ emb, const float* __restrict__ Wih,
                            const float* __restrict__ bih, const float* __restrict__ bhh,
                            float* __restrict__ out) {
    const int v = blockIdx.x;
    __shared__ float er[EMB_];
    er[threadIdx.x] = emb[(size_t)v * EMB_ + threadIdx.x];
    __syncthreads();
    for (int oc = threadIdx.x; oc < N2_; oc += 256) {
        int dd = oc & (DEC_ - 1);
        int g = oc >> 9;
        float acc = bih[oc] + bhh[oc];
#pragma unroll 8
        for (int k = 0; k < EMB_; k++) acc += er[k] * Wih[(size_t)k * N2_ + oc];
        out[(size_t)v * N2_ + dd * 4 + g] = acc;
    }
}

// ---------------------------------------------------------------------------
// Attention: scores from att1+att2, softmax over P, gated awe -> x[:,0:1536],
// copy h -> x[:,1536:2048].
// ---------------------------------------------------------------------------
__global__ void attn_kernel(const float* __restrict__ enc, const float* __restrict__ att1,
                            const float* __restrict__ Wfull,
                            const float* __restrict__ hproj, const float* __restrict__ h,
                            float* __restrict__ x, const int* __restrict__ len, int t) {
    const int b = blockIdx.x;
    if (t >= len[b] - 1) return;
    const int tid = threadIdx.x;
    const int warp = tid >> 5, lane = tid & 31;

    __shared__ float att2s[ATT_];
    __shared__ float wf[ATT_];
    __shared__ float es[P_ + 4];

    att2s[tid] = hproj[(size_t)b * N1_ + tid];
    wf[tid] = Wfull[tid];
    __syncthreads();

    // scores
    for (int p = warp; p < P_; p += 8) {
        const float* a1 = att1 + ((size_t)(b * P_ + p)) * ATT_;
        float part = 0.0f;
#pragma unroll 4
        for (int j = lane; j < ATT_; j += 32)
            part += fmaxf(a1[j] + att2s[j], 0.0f) * wf[j];
#pragma unroll
        for (int o = 16; o; o >>= 1) part += __shfl_xor_sync(0xffffffffu, part, o);
        if (lane == 0) es[p] = part;
    }
    __syncthreads();

    // softmax over P (warp 0)
    if (tid < 32) {
        float m = -1e30f;
        for (int p = tid; p < P_; p += 32) m = fmaxf(m, es[p]);
#pragma unroll
        for (int o = 16; o; o >>= 1) m = fmaxf(m, __shfl_xor_sync(0xffffffffu, m, o));
        float s = 0.0f;
        for (int p = tid; p < P_; p += 32) {
            float ex = expf(es[p] - m);
            es[p] = ex;
            s += ex;
        }
#pragma unroll
        for (int o = 16; o; o >>= 1) s += __shfl_xor_sync(0xffffffffu, s, o);
        float inv = 1.0f / s;
        for (int p = tid; p < P_; p += 32) es[p] *= inv;
    }
    __syncthreads();

    // copy h into x's recurrent slice
    x[(size_t)b * K2_ + 1536 + tid] = h[(size_t)b * DEC_ + tid];
    x[(size_t)b * K2_ + 1536 + 256 + tid] = h[(size_t)b * DEC_ + 256 + tid];

    // gated awe (float4 over ENC)
    const float4* ep0 = (const float4*)(enc + ((size_t)b * P_) * ENC_);
    for (int idx = tid; idx < ENC_ / 4; idx += 256) {
        float ax = 0.f, ay = 0.f, az = 0.f, aw = 0.f;
#pragma unroll 4
        for (int p = 0; p < P_; p++) {
            float4 v = ep0[(size_t)p * (ENC_ / 4) + idx];
            float al = es[p];
            ax += al * v.x; ay += al * v.y; az += al * v.z; aw += al * v.w;
        }
        float4 gl = *(const float4*)(hproj + (size_t)b * N1_ + ATT_ + idx * 4);
        float4 o;
        o.x = ax * sigmoidf_(gl.x);
        o.y = ay * sigmoidf_(gl.y);
        o.z = az * sigmoidf_(gl.z);
        o.w = aw * sigmoidf_(gl.w);
        *(float4*)(x + (size_t)b * K2_ + idx * 4) = o;
    }
}

// ---------------------------------------------------------------------------
// preds[b,t,:] = active ? h[b,:] @ W_fc + b_fc : 0
// ---------------------------------------------------------------------------
__global__ void preds_kernel(const float* __restrict__ Wfc, const float* __restrict__ bfc,
                             const float* __restrict__ h, float* __restrict__ out,
                             const int* __restrict__ len, int t) {
    const int b = blockIdx.x;
    const int tid = threadIdx.x;
    float* o = out + ((size_t)b * T_ + t) * V_;
    if (t >= len[b] - 1) {
        if (tid < V_) o[tid] = 0.0f;
        return;
    }
    __shared__ float hs[DEC_];
    hs[tid] = h[(size_t)b * DEC_ + tid];
    hs[tid + 256] = h[(size_t)b * DEC_ + tid + 256];
    __syncthreads();
    if (tid < V_) {
        float acc = bfc[tid];
#pragma unroll 8
        for (int k = 0; k < DEC_; k++) acc += hs[k] * Wfc[(size_t)k * V_ + tid];
        o[tid] = acc;
    }
}

// ---------------------------------------------------------------------------
extern "C" void kernel_launch(void* const* d_in, const int* in_sizes, int n_in,
                              void* d_out, int out_size) {
    const float* enc        = (const float*)d_in[0];
    const int*   caps       = (const int*)d_in[1];
    const int*   lens       = (const int*)d_in[2];
    const float* emb        = (const float*)d_in[3];
    const float* W_enc_att  = (const float*)d_in[4];
    const float* b_enc_att  = (const float*)d_in[5];
    const float* W_dec_att  = (const float*)d_in[6];
    const float* b_dec_att  = (const float*)d_in[7];
    const float* W_full_att = (const float*)d_in[8];
    // d_in[9] = b_full_att (softmax-invariant; unused)
    const float* W_init_h   = (const float*)d_in[10];
    const float* b_init_h   = (const float*)d_in[11];
    const float* W_init_c   = (const float*)d_in[12];
    const float* b_init_c   = (const float*)d_in[13];
    const float* W_f_beta   = (const float*)d_in[14];
    const float* b_f_beta   = (const float*)d_in[15];
    const float* W_ih       = (const float*)d_in[16];
    const float* b_ih       = (const float*)d_in[17];
    const float* W_hh       = (const float*)d_in[18];
    const float* b_hh       = (const float*)d_in[19];
    const float* W_fc       = (const float*)d_in[20];
    const float* b_fc       = (const float*)d_in[21];
    float* out = (float*)d_out;

    float *ph, *pc, *pmean, *patt1, *phproj, *px, *pWcat1, *pbcat1, *pWcat2, *pembW;
    cudaGetSymbolAddress((void**)&ph,     g_h);
    cudaGetSymbolAddress((void**)&pc,     g_c);
    cudaGetSymbolAddress((void**)&pmean,  g_mean);
    cudaGetSymbolAddress((void**)&patt1,  g_att1);
    cudaGetSymbolAddress((void**)&phproj, g_hproj);
    cudaGetSymbolAddress((void**)&px,     g_x);
    cudaGetSymbolAddress((void**)&pWcat1, g_Wcat1);
    cudaGetSymbolAddress((void**)&pbcat1, g_bcat1);
    cudaGetSymbolAddress((void**)&pWcat2, g_Wcat2);
    cudaGetSymbolAddress((void**)&pembW,  g_embW);

    // ---- precompute ----
    mean_kernel<<<dim3(ENC_ / 256, B_), 256>>>(enc, pmean);
    wcat1_kernel<<<(DEC_ * N1_ + 255) / 256, 256>>>(W_dec_att, W_f_beta, b_dec_att, b_f_beta,
                                                    pWcat1, pbcat1);
    wcat2_kernel<<<(K2_ * N2_ + 255) / 256, 256>>>(W_ih, W_hh, pWcat2);
    embw_kernel<<<V_, 256>>>(emb, W_ih, b_ih, b_hh, pembW);
    // h0, c0
    gemm_f2<false><<<dim3(DEC_ / 128, B_ / 32), 256>>>(pmean, ENC_, W_init_h, DEC_, ENC_,
                                                       b_init_h, ph, nullptr, 0);
    gemm_f2<false><<<dim3(DEC_ / 128, B_ / 32), 256>>>(pmean, ENC_, W_init_c, DEC_, ENC_,
                                                       b_init_c, pc, nullptr, 0);
    // att1 = encoder_out @ W_enc_att + b (M = B*P = 25600)
    gemm_f2<false><<<dim3(ATT_ / 128, (B_ * P_) / 32), 256>>>(enc, ENC_, W_enc_att, ATT_, ENC_,
                                                              b_enc_att, patt1, nullptr, 0);

    // ---- timestep loop ----
    for (int t = 0; t < T_; t++) {
        gemm_f2<true><<<dim3(N1_ / 128, B_ / 32), 256>>>(ph, DEC_, pWcat1, N1_, DEC_,
                                                         pbcat1, phproj, lens, t);
        attn_kernel<<<B_, 256>>>(enc, patt1, W_full_att, phproj, ph, px, lens, t);
        gates_fused<<<dim3(N2_ / 128, B_ / 32), 256>>>(px, pWcat2, pembW, caps, ph, pc,
                                                       lens, t);
        preds_kernel<<<B_, 256>>>(W_fc, b_fc, ph, out, lens, t);
    }
}

// round 4
// speedup vs baseline: 2.2130x; 1.2407x over previous
#include <cuda_runtime.h>
#include <math.h>
#include <mma.h>

using namespace nvcuda;

// Problem constants
#define B_    256
#define P_    100
#define ENC_  1536
#define DEC_  512
#define ATT_  256
#define EMB_  256
#define V_    193
#define T_    150
#define T1_   151
#define N1_   1792   // att2(256) + f_beta(1536)
#define K2_   2048   // awe(1536) + h(512)
#define N2_   2048   // 4*DEC gate-interleaved

// Scratch (device globals: allocation-free per harness rules)
__device__ float g_h[B_ * DEC_];
__device__ float g_c[B_ * DEC_];
__device__ float g_mean[B_ * ENC_];
__device__ float g_att1[B_ * P_ * ATT_];
__device__ float g_hproj[B_ * N1_];
__device__ float g_x[B_ * K2_];          // [gated awe (1536) | h (512)]
__device__ float g_alpha[B_ * P_];
__device__ float g_Wcat1[DEC_ * N1_];    // [W_dec_att | W_f_beta]
__device__ float g_bcat1[N1_];
__device__ float g_Wcat2[K2_ * N2_];     // rows: [W_ih_enc ; W_hh], cols interleaved d*4+g
__device__ float g_embW[V_ * N2_];       // emb@W_ih_emb + b_ih + b_hh, cols interleaved

__device__ __forceinline__ float sigmoidf_(float x) { return 1.0f / (1.0f + expf(-x)); }

__device__ __forceinline__ float tf32r(float x) {
    unsigned int u = __float_as_uint(x), v;
    asm("cvt.rna.tf32.f32 %0, %1;" : "=r"(v) : "r"(u));
    return __uint_as_float(v);
}
__device__ __forceinline__ float4 tf32r4(float4 v) {
    return make_float4(tf32r(v.x), tf32r(v.y), tf32r(v.z), tf32r(v.w));
}

typedef wmma::fragment<wmma::matrix_a, 16, 16, 8, wmma::precision::tf32, wmma::row_major> FragA;
typedef wmma::fragment<wmma::matrix_b, 16, 16, 8, wmma::precision::tf32, wmma::row_major> FragB;
typedef wmma::fragment<wmma::accumulator, 16, 16, 8, float> FragC;

// ---------------------------------------------------------------------------
// tf32 tensor-core 32x128 GEMM tile, BK=32, 256 threads = 8 warps (2 M x 4 N).
// Each warp computes a 16x32 output (2 n-fragments). Inputs rounded to tf32 at
// the smem store; accumulation fp32. Requires K%32==0.
// ---------------------------------------------------------------------------
__device__ __forceinline__ void gemm_tc_tile(const float* __restrict__ A, int lda,
                                             const float* __restrict__ W, int N, int K,
                                             int rows0, int cols0,
                                             float (*As)[36], float (*Bs)[136],
                                             FragC& acc0, FragC& acc1,
                                             int warpM, int warpN) {
    const int tid  = threadIdx.x;
    const int arow = tid >> 3;           // 0..31
    const int acol = (tid & 7) << 2;     // 0..28
    const int brow = tid >> 5;           // 0..7 (+8r)
    const int bcol = (tid & 31) << 2;    // 0..124

    float4 aReg = *(const float4*)(A + (size_t)(rows0 + arow) * lda + acol);
    float4 bReg[4];
#pragma unroll
    for (int r = 0; r < 4; r++)
        bReg[r] = *(const float4*)(W + (size_t)(brow + 8 * r) * N + cols0 + bcol);

    for (int k0 = 0; k0 < K; k0 += 32) {
        *(float4*)&As[arow][acol] = tf32r4(aReg);
#pragma unroll
        for (int r = 0; r < 4; r++)
            *(float4*)&Bs[brow + 8 * r][bcol] = tf32r4(bReg[r]);
        __syncthreads();
        if (k0 + 32 < K) {
            aReg = *(const float4*)(A + (size_t)(rows0 + arow) * lda + k0 + 32 + acol);
#pragma unroll
            for (int r = 0; r < 4; r++)
                bReg[r] = *(const float4*)(W + (size_t)(k0 + 32 + brow + 8 * r) * N + cols0 + bcol);
        }
#pragma unroll
        for (int ks = 0; ks < 4; ks++) {
            FragA af;
            FragB bf0, bf1;
            wmma::load_matrix_sync(af, &As[warpM * 16][ks * 8], 36);
            wmma::load_matrix_sync(bf0, &Bs[ks * 8][warpN * 32], 136);
            wmma::load_matrix_sync(bf1, &Bs[ks * 8][warpN * 32 + 16], 136);
            wmma::mma_sync(acc0, af, bf0, acc0);
            wmma::mma_sync(acc1, af, bf1, acc1);
        }
        __syncthreads();
    }
}

// ---------------------------------------------------------------------------
// Generic tf32 GEMM + bias. SKIP: sorted-length row-tile skip.
// ---------------------------------------------------------------------------
template <bool SKIP>
__global__ void __launch_bounds__(256)
gemm_tc(const float* __restrict__ A, int lda,
        const float* __restrict__ W, int N, int K,
        const float* __restrict__ bias, float* __restrict__ C,
        const int* __restrict__ len, int t) {
    __shared__ __align__(16) float As[32][36];
    __shared__ __align__(16) float Bs[32][136];
    const int rows0 = blockIdx.y * 32;
    if (SKIP) {
        if (t >= len[rows0] - 1) return;
    }
    const int cols0 = blockIdx.x * 128;
    const int warp = threadIdx.x >> 5;
    const int warpM = warp >> 2, warpN = warp & 3;

    FragC acc0, acc1;
    wmma::fill_fragment(acc0, 0.0f);
    wmma::fill_fragment(acc1, 0.0f);
    gemm_tc_tile(A, lda, W, N, K, rows0, cols0, As, Bs, acc0, acc1, warpM, warpN);

    // stage result tile in Bs, then bias + writeout
    wmma::store_matrix_sync(&Bs[warpM * 16][warpN * 32], acc0, 136, wmma::mem_row_major);
    wmma::store_matrix_sync(&Bs[warpM * 16][warpN * 32 + 16], acc1, 136, wmma::mem_row_major);
    __syncthreads();

    const int tid = threadIdx.x;
    const int r = tid >> 3;            // 0..31
    const int cb = (tid & 7) << 4;     // 0..112
#pragma unroll
    for (int u = 0; u < 4; u++) {
        const int col = cb + u * 4;
        float4 v = *(const float4*)&Bs[r][col];
        float4 bv = *(const float4*)(bias + cols0 + col);
        v.x += bv.x; v.y += bv.y; v.z += bv.z; v.w += bv.w;
        *(float4*)(C + (size_t)(rows0 + r) * N + cols0 + col) = v;
    }
}

// ---------------------------------------------------------------------------
// Fused gates GEMM (tf32) + LSTM cell. A = g_x [awe|h] (K=2048), W = g_Wcat2
// (cols interleaved d*4+g). Epilogue adds embW[token] (b_ih+b_hh included),
// then i,f,g,o -> c,h update, masked per row.
// ---------------------------------------------------------------------------
__global__ void __launch_bounds__(256)
gates_tc(const float* __restrict__ x, const float* __restrict__ W,
         const float* __restrict__ embW, const int* __restrict__ caps,
         float* __restrict__ h, float* __restrict__ c,
         const int* __restrict__ len, int t) {
    __shared__ __align__(16) float As[32][36];
    __shared__ __align__(16) float Bs[32][136];
    const int rows0 = blockIdx.y * 32;
    if (t >= len[rows0] - 1) return;
    const int cols0 = blockIdx.x * 128;
    const int warp = threadIdx.x >> 5;
    const int warpM = warp >> 2, warpN = warp & 3;

    FragC acc0, acc1;
    wmma::fill_fragment(acc0, 0.0f);
    wmma::fill_fragment(acc1, 0.0f);
    gemm_tc_tile(x, K2_, W, N2_, K2_, rows0, cols0, As, Bs, acc0, acc1, warpM, warpN);

    wmma::store_matrix_sync(&Bs[warpM * 16][warpN * 32], acc0, 136, wmma::mem_row_major);
    wmma::store_matrix_sync(&Bs[warpM * 16][warpN * 32 + 16], acc1, 136, wmma::mem_row_major);
    __syncthreads();

    const int tid = threadIdx.x;
    const int r = tid >> 3;            // 0..31
    const int cb = (tid & 7) << 4;     // 0..112
    const int b = rows0 + r;
    if (t >= len[b] - 1) return;
    const int token = caps[b * T1_ + t];

#pragma unroll
    for (int u = 0; u < 4; u++) {
        const int cp = cols0 + cb + u * 4;   // global interleaved col (= d*4+gate)
        const int d = cp >> 2;
        float4 gv = *(const float4*)&Bs[r][cb + u * 4];
        float4 ew = *(const float4*)(embW + (size_t)token * N2_ + cp);
        float vi = gv.x + ew.x;
        float vf = gv.y + ew.y;
        float vg = gv.z + ew.z;
        float vo = gv.w + ew.w;
        float c_old = c[(size_t)b * DEC_ + d];
        float ii = sigmoidf_(vi);
        float ff = sigmoidf_(vf);
        float gg = tanhf(vg);
        float oo = sigmoidf_(vo);
        float cn = ff * c_old + ii * gg;
        float hn = oo * tanhf(cn);
        c[(size_t)b * DEC_ + d] = cn;
        h[(size_t)b * DEC_ + d] = hn;
    }
}

// ---------------------------------------------------------------------------
// mean_enc[b,e] = mean over P of encoder_out[b,p,e]
// ---------------------------------------------------------------------------
__global__ void mean_kernel(const float* __restrict__ enc, float* __restrict__ mean) {
    const int b = blockIdx.y;
    const int e = blockIdx.x * 256 + threadIdx.x;
    const float* ep = enc + ((size_t)b * P_) * ENC_ + e;
    float s = 0.0f;
#pragma unroll 4
    for (int p = 0; p < P_; p++) s += ep[(size_t)p * ENC_];
    mean[(size_t)b * ENC_ + e] = s * (1.0f / P_);
}

// ---------------------------------------------------------------------------
// Weight prep
// ---------------------------------------------------------------------------
__global__ void wcat1_kernel(const float* __restrict__ Wda, const float* __restrict__ Wfb,
                             const float* __restrict__ bda, const float* __restrict__ bfb,
                             float* __restrict__ Wc, float* __restrict__ bc) {
    int idx = blockIdx.x * 256 + threadIdx.x;
    if (idx >= DEC_ * N1_) return;
    int k = idx / N1_, n = idx % N1_;
    Wc[idx] = (n < ATT_) ? Wda[k * ATT_ + n] : Wfb[k * ENC_ + (n - ATT_)];
    if (k == 0) bc[n] = (n < ATT_) ? bda[n] : bfb[n - ATT_];
}

__global__ void wcat2_kernel(const float* __restrict__ Wih, const float* __restrict__ Whh,
                             float* __restrict__ Wc) {
    int idx = blockIdx.x * 256 + threadIdx.x;
    if (idx >= K2_ * N2_) return;
    int k = idx / N2_, cp = idx % N2_;
    int dd = cp >> 2, g = cp & 3;
    int oc = g * DEC_ + dd;
    Wc[idx] = (k < 1536) ? Wih[(size_t)(256 + k) * N2_ + oc]
                         : Whh[(size_t)(k - 1536) * N2_ + oc];
}

// embW[v, d*4+g] = sum_k emb[v,k] * W_ih[k, g*512+d] + b_ih + b_hh (fp32)
__global__ void embw_kernel(const float* __restrict__ emb, const float* __restrict__ Wih,
                            const float* __restrict__ bih, const float* __restrict__ bhh,
                            float* __restrict__ out) {
    const int v = blockIdx.x;
    __shared__ float er[EMB_];
    er[threadIdx.x] = emb[(size_t)v * EMB_ + threadIdx.x];
    __syncthreads();
    for (int oc = threadIdx.x; oc < N2_; oc += 256) {
        int dd = oc & (DEC_ - 1);
        int g = oc >> 9;
        float acc = bih[oc] + bhh[oc];
#pragma unroll 8
        for (int k = 0; k < EMB_; k++) acc += er[k] * Wih[(size_t)k * N2_ + oc];
        out[(size_t)v * N2_ + dd * 4 + g] = acc;
    }
}

// ---------------------------------------------------------------------------
// Scores + softmax: alpha[b,p] = softmax_p( relu(att1+att2).Wfull ).
// Also copies h into x's recurrent slice.
// ---------------------------------------------------------------------------
__global__ void attn_scores(const float* __restrict__ att1, const float* __restrict__ Wfull,
                            const float* __restrict__ hproj, const float* __restrict__ h,
                            float* __restrict__ alpha, float* __restrict__ x,
                            const int* __restrict__ len, int t) {
    const int b = blockIdx.x;
    if (t >= len[b] - 1) return;
    const int tid = threadIdx.x;
    const int warp = tid >> 5, lane = tid & 31;

    __shared__ float att2s[ATT_];
    __shared__ float wf[ATT_];
    __shared__ float es[P_ + 4];

    att2s[tid] = hproj[(size_t)b * N1_ + tid];
    wf[tid] = Wfull[tid];
    __syncthreads();

    for (int p = warp; p < P_; p += 8) {
        const float* a1 = att1 + ((size_t)(b * P_ + p)) * ATT_;
        float part = 0.0f;
#pragma unroll 4
        for (int j = lane; j < ATT_; j += 32)
            part += fmaxf(a1[j] + att2s[j], 0.0f) * wf[j];
#pragma unroll
        for (int o = 16; o; o >>= 1) part += __shfl_xor_sync(0xffffffffu, part, o);
        if (lane == 0) es[p] = part;
    }
    __syncthreads();

    if (tid < 32) {
        float m = -1e30f;
        for (int p = tid; p < P_; p += 32) m = fmaxf(m, es[p]);
#pragma unroll
        for (int o = 16; o; o >>= 1) m = fmaxf(m, __shfl_xor_sync(0xffffffffu, m, o));
        float s = 0.0f;
        for (int p = tid; p < P_; p += 32) {
            float ex = expf(es[p] - m);
            es[p] = ex;
            s += ex;
        }
#pragma unroll
        for (int o = 16; o; o >>= 1) s += __shfl_xor_sync(0xffffffffu, s, o);
        float inv = 1.0f / s;
        for (int p = tid; p < P_; p += 32) es[p] *= inv;
    }
    __syncthreads();

    if (tid < P_) alpha[b * P_ + tid] = es[tid];
    x[(size_t)b * K2_ + 1536 + tid] = h[(size_t)b * DEC_ + tid];
    x[(size_t)b * K2_ + 1536 + 256 + tid] = h[(size_t)b * DEC_ + 256 + tid];
}

// ---------------------------------------------------------------------------
// awe: x[b, chunk] = sigmoid(gate) * sum_p alpha[b,p] * enc[b,p,chunk].
// grid (3, B): each block handles a 512-float chunk of ENC with 128 threads.
// ---------------------------------------------------------------------------
__global__ void awe_kernel(const float* __restrict__ enc, const float* __restrict__ alpha,
                           const float* __restrict__ hproj, float* __restrict__ x,
                           const int* __restrict__ len, int t) {
    const int b = blockIdx.y;
    if (t >= len[b] - 1) return;
    const int tid = threadIdx.x;
    const int chunk0 = blockIdx.x * 512;        // float offset within ENC

    __shared__ float al[P_];
    if (tid < P_) al[tid] = alpha[b * P_ + tid];
    __syncthreads();

    const float4* ep = (const float4*)(enc + ((size_t)b * P_) * ENC_ + chunk0);
    float4 acc = make_float4(0.f, 0.f, 0.f, 0.f);
#pragma unroll 4
    for (int p = 0; p < P_; p++) {
        float4 v = ep[(size_t)p * (ENC_ / 4) + tid];
        float a = al[p];
        acc.x += a * v.x; acc.y += a * v.y; acc.z += a * v.z; acc.w += a * v.w;
    }
    const int col = chunk0 + tid * 4;
    float4 gl = *(const float4*)(hproj + (size_t)b * N1_ + ATT_ + col);
    float4 o;
    o.x = acc.x * sigmoidf_(gl.x);
    o.y = acc.y * sigmoidf_(gl.y);
    o.z = acc.z * sigmoidf_(gl.z);
    o.w = acc.w * sigmoidf_(gl.w);
    *(float4*)(x + (size_t)b * K2_ + col) = o;
}

// ---------------------------------------------------------------------------
// preds[b,t,:] = active ? h[b,:] @ W_fc + b_fc : 0
// ---------------------------------------------------------------------------
__global__ void preds_kernel(const float* __restrict__ Wfc, const float* __restrict__ bfc,
                             const float* __restrict__ h, float* __restrict__ out,
                             const int* __restrict__ len, int t) {
    const int b = blockIdx.x;
    const int tid = threadIdx.x;
    float* o = out + ((size_t)b * T_ + t) * V_;
    if (t >= len[b] - 1) {
        if (tid < V_) o[tid] = 0.0f;
        return;
    }
    __shared__ float hs[DEC_];
    hs[tid] = h[(size_t)b * DEC_ + tid];
    hs[tid + 256] = h[(size_t)b * DEC_ + tid + 256];
    __syncthreads();
    if (tid < V_) {
        float acc = bfc[tid];
#pragma unroll 8
        for (int k = 0; k < DEC_; k++) acc += hs[k] * Wfc[(size_t)k * V_ + tid];
        o[tid] = acc;
    }
}

// ---------------------------------------------------------------------------
extern "C" void kernel_launch(void* const* d_in, const int* in_sizes, int n_in,
                              void* d_out, int out_size) {
    const float* enc        = (const float*)d_in[0];
    const int*   caps       = (const int*)d_in[1];
    const int*   lens       = (const int*)d_in[2];
    const float* emb        = (const float*)d_in[3];
    const float* W_enc_att  = (const float*)d_in[4];
    const float* b_enc_att  = (const float*)d_in[5];
    const float* W_dec_att  = (const float*)d_in[6];
    const float* b_dec_att  = (const float*)d_in[7];
    const float* W_full_att = (const float*)d_in[8];
    // d_in[9] = b_full_att (softmax-invariant; unused)
    const float* W_init_h   = (const float*)d_in[10];
    const float* b_init_h   = (const float*)d_in[11];
    const float* W_init_c   = (const float*)d_in[12];
    const float* b_init_c   = (const float*)d_in[13];
    const float* W_f_beta   = (const float*)d_in[14];
    const float* b_f_beta   = (const float*)d_in[15];
    const float* W_ih       = (const float*)d_in[16];
    const float* b_ih       = (const float*)d_in[17];
    const float* W_hh       = (const float*)d_in[18];
    const float* b_hh       = (const float*)d_in[19];
    const float* W_fc       = (const float*)d_in[20];
    const float* b_fc       = (const float*)d_in[21];
    float* out = (float*)d_out;

    float *ph, *pc, *pmean, *patt1, *phproj, *px, *palpha, *pWcat1, *pbcat1, *pWcat2, *pembW;
    cudaGetSymbolAddress((void**)&ph,     g_h);
    cudaGetSymbolAddress((void**)&pc,     g_c);
    cudaGetSymbolAddress((void**)&pmean,  g_mean);
    cudaGetSymbolAddress((void**)&patt1,  g_att1);
    cudaGetSymbolAddress((void**)&phproj, g_hproj);
    cudaGetSymbolAddress((void**)&px,     g_x);
    cudaGetSymbolAddress((void**)&palpha, g_alpha);
    cudaGetSymbolAddress((void**)&pWcat1, g_Wcat1);
    cudaGetSymbolAddress((void**)&pbcat1, g_bcat1);
    cudaGetSymbolAddress((void**)&pWcat2, g_Wcat2);
    cudaGetSymbolAddress((void**)&pembW,  g_embW);

    // ---- precompute ----
    mean_kernel<<<dim3(ENC_ / 256, B_), 256>>>(enc, pmean);
    wcat1_kernel<<<(DEC_ * N1_ + 255) / 256, 256>>>(W_dec_att, W_f_beta, b_dec_att, b_f_beta,
                                                    pWcat1, pbcat1);
    wcat2_kernel<<<(K2_ * N2_ + 255) / 256, 256>>>(W_ih, W_hh, pWcat2);
    embw_kernel<<<V_, 256>>>(emb, W_ih, b_ih, b_hh, pembW);
    // h0, c0
    gemm_tc<false><<<dim3(DEC_ / 128, B_ / 32), 256>>>(pmean, ENC_, W_init_h, DEC_, ENC_,
                                                       b_init_h, ph, nullptr, 0);
    gemm_tc<false><<<dim3(DEC_ / 128, B_ / 32), 256>>>(pmean, ENC_, W_init_c, DEC_, ENC_,
                                                       b_init_c, pc, nullptr, 0);
    // att1 = encoder_out @ W_enc_att + b (M = B*P = 25600)
    gemm_tc<false><<<dim3(ATT_ / 128, (B_ * P_) / 32), 256>>>(enc, ENC_, W_enc_att, ATT_, ENC_,
                                                              b_enc_att, patt1, nullptr, 0);

    // ---- timestep loop ----
    for (int t = 0; t < T_; t++) {
        gemm_tc<true><<<dim3(N1_ / 128, B_ / 32), 256>>>(ph, DEC_, pWcat1, N1_, DEC_,
                                                         pbcat1, phproj, lens, t);
        attn_scores<<<B_, 256>>>(patt1, W_full_att, phproj, ph, palpha, px, lens, t);
        awe_kernel<<<dim3(3, B_), 128>>>(enc, palpha, phproj, px, lens, t);
        gates_tc<<<dim3(N2_ / 128, B_ / 32), 256>>>(px, pWcat2, pembW, caps, ph, pc,
                                                    lens, t);
        preds_kernel<<<B_, 256>>>(W_fc, b_fc, ph, out, lens, t);
    }
}